// round 4
// baseline (speedup 1.0000x reference)
#include <cuda_runtime.h>
#include <math.h>

// Problem constants (fixed by the harness inputs)
#define BB   4
#define CC   128
#define IC   64
#define NN   4096     // H*W = 64*64

// ---------------------------------------------------------------------------
// Scratch (device globals: allocation-free rule)
// ---------------------------------------------------------------------------
__device__ float d_theta[BB * NN * IC];   // [b][n][i]
__device__ float d_gx   [BB * NN * IC];   // [b][n][i]
__device__ float d_phi  [BB * IC * NN];   // [b][i][n]
__device__ float d_y    [BB * NN * IC];   // [b][n][i]

// ---------------------------------------------------------------------------
// Kernel 1: 1x1-conv projections.  out[i][n] = sum_c w[i][c] * x[b][c][n] + b[i]
// grid (N/64, 3, B), 256 threads.  Each block: one projection, 64 i x 64 n tile.
// ---------------------------------------------------------------------------
__global__ __launch_bounds__(256)
void proj_kernel(const float* __restrict__ x,
                 const float* __restrict__ g_w,  const float* __restrict__ g_b,
                 const float* __restrict__ th_w, const float* __restrict__ th_b,
                 const float* __restrict__ ph_w, const float* __restrict__ ph_b)
{
    extern __shared__ float sm[];
    float* xs = sm;               // [128][64]  xs[c][n]
    float* ws = sm + 128 * 64;    // [64][128]  natural copy of w[i][c]

    const int n0 = blockIdx.x * 64;
    const int p  = blockIdx.y;            // 0=g, 1=theta, 2=phi
    const int b  = blockIdx.z;
    const float* w    = (p == 0) ? g_w : (p == 1) ? th_w : ph_w;
    const float* bias = (p == 0) ? g_b : (p == 1) ? th_b : ph_b;

    const int tid = threadIdx.x;

    // Load x tile: x[b][c][n0..n0+63]
    {
        const float* xb = x + (size_t)b * CC * NN;
        const int n4 = (tid & 15) * 4;
        for (int c = (tid >> 4); c < 128; c += 16) {
            float4 v = *(const float4*)(xb + (size_t)c * NN + n0 + n4);
            *(float4*)(xs + c * 64 + n4) = v;
        }
    }
    // Load weights (64*128 floats = 2048 float4)
    {
        const float4* src = (const float4*)w;
        float4* dst = (float4*)ws;
        for (int i = tid; i < 2048; i += 256) dst[i] = src[i];
    }
    __syncthreads();

    const int ty = tid >> 4, tx = tid & 15;
    const int i0 = ty * 4, j0 = tx * 4;

    float acc[4][4] = {};
    #pragma unroll 8
    for (int c = 0; c < 128; c++) {
        float4 xv = *(const float4*)(xs + c * 64 + j0);
        float w0 = ws[(i0 + 0) * 128 + c];
        float w1 = ws[(i0 + 1) * 128 + c];
        float w2 = ws[(i0 + 2) * 128 + c];
        float w3 = ws[(i0 + 3) * 128 + c];
        acc[0][0] = fmaf(w0, xv.x, acc[0][0]); acc[0][1] = fmaf(w0, xv.y, acc[0][1]);
        acc[0][2] = fmaf(w0, xv.z, acc[0][2]); acc[0][3] = fmaf(w0, xv.w, acc[0][3]);
        acc[1][0] = fmaf(w1, xv.x, acc[1][0]); acc[1][1] = fmaf(w1, xv.y, acc[1][1]);
        acc[1][2] = fmaf(w1, xv.z, acc[1][2]); acc[1][3] = fmaf(w1, xv.w, acc[1][3]);
        acc[2][0] = fmaf(w2, xv.x, acc[2][0]); acc[2][1] = fmaf(w2, xv.y, acc[2][1]);
        acc[2][2] = fmaf(w2, xv.z, acc[2][2]); acc[2][3] = fmaf(w2, xv.w, acc[2][3]);
        acc[3][0] = fmaf(w3, xv.x, acc[3][0]); acc[3][1] = fmaf(w3, xv.y, acc[3][1]);
        acc[3][2] = fmaf(w3, xv.z, acc[3][2]); acc[3][3] = fmaf(w3, xv.w, acc[3][3]);
    }

    if (p == 2) {
        // phi: [b][i][n]
        #pragma unroll
        for (int ii = 0; ii < 4; ii++) {
            float bi = bias[i0 + ii];
            float4 o = make_float4(acc[ii][0] + bi, acc[ii][1] + bi,
                                   acc[ii][2] + bi, acc[ii][3] + bi);
            *(float4*)(d_phi + ((size_t)b * IC + i0 + ii) * NN + n0 + j0) = o;
        }
    } else {
        float* dst = (p == 0) ? d_gx : d_theta;  // [b][n][i]
        float b0 = bias[i0], b1 = bias[i0+1], b2 = bias[i0+2], b3 = bias[i0+3];
        #pragma unroll
        for (int jj = 0; jj < 4; jj++) {
            float4 o = make_float4(acc[0][jj] + b0, acc[1][jj] + b1,
                                   acc[2][jj] + b2, acc[3][jj] + b3);
            *(float4*)(dst + ((size_t)b * NN + n0 + j0 + jj) * IC + i0) = o;
        }
    }
}

// ---------------------------------------------------------------------------
// Kernel 2: flash attention core.
//   f[r][m] = sum_k theta[r][k] * phi[k][m]   (no scale!)
//   y[r][:] = softmax_m(f[r][:]) @ g[m][:]
// grid (N/64, B), 256 threads.  64x64 Q-row tile per block, stream over 64
// 64-wide K/V tiles with online softmax.
// Double-buffered K/V smem (ONE barrier per tile) + register prefetch two
// tiles ahead + half-warp P exchange (no block barrier for P).
// Smem 100352 B, <=128 regs -> 2 CTAs/SM.
// ---------------------------------------------------------------------------
#define QT_PITCH 68   // pad: transpose-write conflicts 16-way -> 2-way
#define PS_PITCH 68   // pad: row stride 68 -> ty-groups 16 banks apart, conflict-free
#define NT       (NN / 64)

__global__ __launch_bounds__(256, 2)
void flash_kernel()
{
    extern __shared__ float sm[];
    float* Qt  = sm;                        // [64][68]  Qt[k][r]
    float* Ks0 = Qt + 64 * QT_PITCH;        // [64][64]  Ks[k][m]  buffer 0
    float* Vs0 = Ks0 + 64 * 64;             // [64][64]  Vs[m][j]  buffer 0
    float* Ks1 = Vs0 + 64 * 64;             // buffer 1
    float* Vs1 = Ks1 + 64 * 64;             // buffer 1
    float* Ps  = Vs1 + 64 * 64;             // [64][68]  Ps[r][m]

    const int r0  = blockIdx.x * 64;
    const int b   = blockIdx.y;
    const int tid = threadIdx.x;
    const int ty  = tid >> 4, tx = tid & 15;

    const float* theta = d_theta + (size_t)b * NN * IC;
    const float* phi   = d_phi   + (size_t)b * IC * NN;
    const float* g     = d_gx    + (size_t)b * NN * IC;
    float*       yb    = d_y     + (size_t)b * NN * IC;

    // Load Q tile transposed: Qt[k][r] = theta[r0+r][k]
    {
        const int k4 = (tid & 15) * 4;
        for (int r = (tid >> 4); r < 64; r += 16) {
            float4 v = *(const float4*)(theta + (size_t)(r0 + r) * IC + k4);
            Qt[(k4 + 0) * QT_PITCH + r] = v.x;
            Qt[(k4 + 1) * QT_PITCH + r] = v.y;
            Qt[(k4 + 2) * QT_PITCH + r] = v.z;
            Qt[(k4 + 3) * QT_PITCH + r] = v.w;
        }
    }

    // Per-thread staged K/V fragments for the software pipeline.
    // K: rows k = ty + 16*u, cols tx*4..   V: rows m likewise.
    const int c4 = tx * 4;
    float4 kd[4], vd[4];

    // Prologue: tile 0 -> regs -> buf0; tile 1 -> regs.
    #pragma unroll
    for (int u = 0; u < 4; u++) {
        const int row = ty + 16 * u;
        kd[u] = *(const float4*)(phi + (size_t)row * NN + c4);
        vd[u] = *(const float4*)(g + (size_t)row * IC + c4);
    }
    #pragma unroll
    for (int u = 0; u < 4; u++) {
        const int row = ty + 16 * u;
        *(float4*)(Ks0 + row * 64 + c4) = kd[u];
        *(float4*)(Vs0 + row * 64 + c4) = vd[u];
    }
    #pragma unroll
    for (int u = 0; u < 4; u++) {
        const int row = ty + 16 * u;
        kd[u] = *(const float4*)(phi + (size_t)row * NN + 64 + c4);
        vd[u] = *(const float4*)(g + (size_t)(64 + row) * IC + c4);
    }

    float o[4][4] = {};
    float m_r[4] = {-1e30f, -1e30f, -1e30f, -1e30f};
    float l_r[4] = {};

    for (int t = 0; t < NT; t++) {
        // One barrier per tile: all warps finished reading buf[(t+1)&1]
        // (tile t-1) AND tile t's commit (done last iteration) is visible.
        __syncthreads();

        float* Ks = (t & 1) ? Ks1 : Ks0;
        float* Vs = (t & 1) ? Vs1 : Vs0;

        // Commit tile t+1 (staged in regs) into the other buffer.
        if (t + 1 < NT) {
            float* Ksn = (t & 1) ? Ks0 : Ks1;
            float* Vsn = (t & 1) ? Vs0 : Vs1;
            #pragma unroll
            for (int u = 0; u < 4; u++) {
                const int row = ty + 16 * u;
                *(float4*)(Ksn + row * 64 + c4) = kd[u];
                *(float4*)(Vsn + row * 64 + c4) = vd[u];
            }
        }
        // Prefetch tile t+2 into regs (consumed two iterations from now).
        if (t + 2 < NT) {
            const int m0n = (t + 2) * 64;
            #pragma unroll
            for (int u = 0; u < 4; u++) {
                const int row = ty + 16 * u;
                kd[u] = *(const float4*)(phi + (size_t)row * NN + m0n + c4);
                vd[u] = *(const float4*)(g + (size_t)(m0n + row) * IC + c4);
            }
        }

        // S = Q @ K  (thread: rows ty*4.., cols tx*4..)
        float s[4][4] = {};
        #pragma unroll 8
        for (int k = 0; k < 64; k++) {
            float4 qv = *(const float4*)(Qt + k * QT_PITCH + ty * 4);
            float4 kv = *(const float4*)(Ks + k * 64 + tx * 4);
            s[0][0]=fmaf(qv.x,kv.x,s[0][0]); s[0][1]=fmaf(qv.x,kv.y,s[0][1]);
            s[0][2]=fmaf(qv.x,kv.z,s[0][2]); s[0][3]=fmaf(qv.x,kv.w,s[0][3]);
            s[1][0]=fmaf(qv.y,kv.x,s[1][0]); s[1][1]=fmaf(qv.y,kv.y,s[1][1]);
            s[1][2]=fmaf(qv.y,kv.z,s[1][2]); s[1][3]=fmaf(qv.y,kv.w,s[1][3]);
            s[2][0]=fmaf(qv.z,kv.x,s[2][0]); s[2][1]=fmaf(qv.z,kv.y,s[2][1]);
            s[2][2]=fmaf(qv.z,kv.z,s[2][2]); s[2][3]=fmaf(qv.z,kv.w,s[2][3]);
            s[3][0]=fmaf(qv.w,kv.x,s[3][0]); s[3][1]=fmaf(qv.w,kv.y,s[3][1]);
            s[3][2]=fmaf(qv.w,kv.z,s[3][2]); s[3][3]=fmaf(qv.w,kv.w,s[3][3]);
        }

        // Online softmax per row (row split over the 16 tx lanes of a half-warp)
        #pragma unroll
        for (int rr = 0; rr < 4; rr++) {
            float mx = fmaxf(fmaxf(s[rr][0], s[rr][1]), fmaxf(s[rr][2], s[rr][3]));
            mx = fmaxf(mx, __shfl_xor_sync(0xffffffffu, mx, 1));
            mx = fmaxf(mx, __shfl_xor_sync(0xffffffffu, mx, 2));
            mx = fmaxf(mx, __shfl_xor_sync(0xffffffffu, mx, 4));
            mx = fmaxf(mx, __shfl_xor_sync(0xffffffffu, mx, 8));
            float mnew = fmaxf(m_r[rr], mx);
            float al   = __expf(m_r[rr] - mnew);
            float p0 = __expf(s[rr][0] - mnew);
            float p1 = __expf(s[rr][1] - mnew);
            float p2 = __expf(s[rr][2] - mnew);
            float p3 = __expf(s[rr][3] - mnew);
            float sum = p0 + p1 + p2 + p3;
            sum += __shfl_xor_sync(0xffffffffu, sum, 1);
            sum += __shfl_xor_sync(0xffffffffu, sum, 2);
            sum += __shfl_xor_sync(0xffffffffu, sum, 4);
            sum += __shfl_xor_sync(0xffffffffu, sum, 8);
            l_r[rr] = l_r[rr] * al + sum;
            m_r[rr] = mnew;
            o[rr][0] *= al; o[rr][1] *= al; o[rr][2] *= al; o[rr][3] *= al;
            // stage P row segment (contiguous float4 STS.128)
            *(float4*)(Ps + (ty * 4 + rr) * PS_PITCH + tx * 4) = make_float4(p0, p1, p2, p3);
        }
        // P rows ty*4..ty*4+3 are produced and consumed entirely within this
        // half-warp's 16 lanes (same ty) -> warp-level sync suffices.
        __syncwarp();

        // O += P @ V  (thread: rows ty*4.., j-cols tx*4..)
        // Chunked by 4 m-steps: P rows loaded as float4 (broadcast, conflict-free
        // with PS_PITCH=68) instead of per-m scalar same-bank loads.
        #pragma unroll 4
        for (int m4 = 0; m4 < 64; m4 += 4) {
            float4 pa = *(const float4*)(Ps + (ty * 4 + 0) * PS_PITCH + m4);
            float4 pb = *(const float4*)(Ps + (ty * 4 + 1) * PS_PITCH + m4);
            float4 pc = *(const float4*)(Ps + (ty * 4 + 2) * PS_PITCH + m4);
            float4 pd = *(const float4*)(Ps + (ty * 4 + 3) * PS_PITCH + m4);

            float4 vv;
            vv = *(const float4*)(Vs + (m4 + 0) * 64 + tx * 4);
            o[0][0]=fmaf(pa.x,vv.x,o[0][0]); o[0][1]=fmaf(pa.x,vv.y,o[0][1]);
            o[0][2]=fmaf(pa.x,vv.z,o[0][2]); o[0][3]=fmaf(pa.x,vv.w,o[0][3]);
            o[1][0]=fmaf(pb.x,vv.x,o[1][0]); o[1][1]=fmaf(pb.x,vv.y,o[1][1]);
            o[1][2]=fmaf(pb.x,vv.z,o[1][2]); o[1][3]=fmaf(pb.x,vv.w,o[1][3]);
            o[2][0]=fmaf(pc.x,vv.x,o[2][0]); o[2][1]=fmaf(pc.x,vv.y,o[2][1]);
            o[2][2]=fmaf(pc.x,vv.z,o[2][2]); o[2][3]=fmaf(pc.x,vv.w,o[2][3]);
            o[3][0]=fmaf(pd.x,vv.x,o[3][0]); o[3][1]=fmaf(pd.x,vv.y,o[3][1]);
            o[3][2]=fmaf(pd.x,vv.z,o[3][2]); o[3][3]=fmaf(pd.x,vv.w,o[3][3]);

            vv = *(const float4*)(Vs + (m4 + 1) * 64 + tx * 4);
            o[0][0]=fmaf(pa.y,vv.x,o[0][0]); o[0][1]=fmaf(pa.y,vv.y,o[0][1]);
            o[0][2]=fmaf(pa.y,vv.z,o[0][2]); o[0][3]=fmaf(pa.y,vv.w,o[0][3]);
            o[1][0]=fmaf(pb.y,vv.x,o[1][0]); o[1][1]=fmaf(pb.y,vv.y,o[1][1]);
            o[1][2]=fmaf(pb.y,vv.z,o[1][2]); o[1][3]=fmaf(pb.y,vv.w,o[1][3]);
            o[2][0]=fmaf(pc.y,vv.x,o[2][0]); o[2][1]=fmaf(pc.y,vv.y,o[2][1]);
            o[2][2]=fmaf(pc.y,vv.z,o[2][2]); o[2][3]=fmaf(pc.y,vv.w,o[2][3]);
            o[3][0]=fmaf(pd.y,vv.x,o[3][0]); o[3][1]=fmaf(pd.y,vv.y,o[3][1]);
            o[3][2]=fmaf(pd.y,vv.z,o[3][2]); o[3][3]=fmaf(pd.y,vv.w,o[3][3]);

            vv = *(const float4*)(Vs + (m4 + 2) * 64 + tx * 4);
            o[0][0]=fmaf(pa.z,vv.x,o[0][0]); o[0][1]=fmaf(pa.z,vv.y,o[0][1]);
            o[0][2]=fmaf(pa.z,vv.z,o[0][2]); o[0][3]=fmaf(pa.z,vv.w,o[0][3]);
            o[1][0]=fmaf(pb.z,vv.x,o[1][0]); o[1][1]=fmaf(pb.z,vv.y,o[1][1]);
            o[1][2]=fmaf(pb.z,vv.z,o[1][2]); o[1][3]=fmaf(pb.z,vv.w,o[1][3]);
            o[2][0]=fmaf(pc.z,vv.x,o[2][0]); o[2][1]=fmaf(pc.z,vv.y,o[2][1]);
            o[2][2]=fmaf(pc.z,vv.z,o[2][2]); o[2][3]=fmaf(pc.z,vv.w,o[2][3]);
            o[3][0]=fmaf(pd.z,vv.x,o[3][0]); o[3][1]=fmaf(pd.z,vv.y,o[3][1]);
            o[3][2]=fmaf(pd.z,vv.z,o[3][2]); o[3][3]=fmaf(pd.z,vv.w,o[3][3]);

            vv = *(const float4*)(Vs + (m4 + 3) * 64 + tx * 4);
            o[0][0]=fmaf(pa.w,vv.x,o[0][0]); o[0][1]=fmaf(pa.w,vv.y,o[0][1]);
            o[0][2]=fmaf(pa.w,vv.z,o[0][2]); o[0][3]=fmaf(pa.w,vv.w,o[0][3]);
            o[1][0]=fmaf(pb.w,vv.x,o[1][0]); o[1][1]=fmaf(pb.w,vv.y,o[1][1]);
            o[1][2]=fmaf(pb.w,vv.z,o[1][2]); o[1][3]=fmaf(pb.w,vv.w,o[1][3]);
            o[2][0]=fmaf(pc.w,vv.x,o[2][0]); o[2][1]=fmaf(pc.w,vv.y,o[2][1]);
            o[2][2]=fmaf(pc.w,vv.z,o[2][2]); o[2][3]=fmaf(pc.w,vv.w,o[2][3]);
            o[3][0]=fmaf(pd.w,vv.x,o[3][0]); o[3][1]=fmaf(pd.w,vv.y,o[3][1]);
            o[3][2]=fmaf(pd.w,vv.z,o[3][2]); o[3][3]=fmaf(pd.w,vv.w,o[3][3]);
        }
    }

    // Normalize and store y[b][r][j]
    #pragma unroll
    for (int rr = 0; rr < 4; rr++) {
        float inv = 1.0f / l_r[rr];
        float4 ov = make_float4(o[rr][0] * inv, o[rr][1] * inv,
                                o[rr][2] * inv, o[rr][3] * inv);
        *(float4*)(yb + (size_t)(r0 + ty * 4 + rr) * IC + tx * 4) = ov;
    }
}

// ---------------------------------------------------------------------------
// Kernel 3: output projection + residual.
//   out[b][c][n] = sum_i W_w[c][i] * y[b][n][i] + W_b[c] + x[b][c][n]
// grid (N/64, B), 256 threads.  Thread tile: 8 c x 4 n.
// ---------------------------------------------------------------------------
#define YS_PITCH 68

__global__ __launch_bounds__(256)
void outproj_kernel(const float* __restrict__ x,
                    const float* __restrict__ W_w,
                    const float* __restrict__ W_b,
                    float* __restrict__ out)
{
    extern __shared__ float sm[];
    float* wws = sm;               // [128][64]  natural copy of W_w[c][i]
    float* ys  = sm + 128 * 64;    // [64][68]   ys[n][i]

    const int n0  = blockIdx.x * 64;
    const int b   = blockIdx.y;
    const int tid = threadIdx.x;

    // Load W_w (128*64 floats = 2048 float4)
    {
        const float4* src = (const float4*)W_w;
        float4* dst = (float4*)wws;
        for (int i = tid; i < 2048; i += 256) dst[i] = src[i];
    }
    // Load y tile: ys[n][i] = y[b][n0+n][i]
    {
        const float* yb = d_y + (size_t)b * NN * IC;
        const int i4 = (tid & 15) * 4;
        for (int n = (tid >> 4); n < 64; n += 16) {
            *(float4*)(ys + n * YS_PITCH + i4) =
                *(const float4*)(yb + (size_t)(n0 + n) * IC + i4);
        }
    }
    __syncthreads();

    const int ty = tid >> 4, tx = tid & 15;
    const int c0 = ty * 8, n4 = tx * 4;

    float acc[8][4] = {};
    #pragma unroll 4
    for (int i4 = 0; i4 < 64; i4 += 4) {
        float4 yv0 = *(const float4*)(ys + (n4 + 0) * YS_PITCH + i4);
        float4 yv1 = *(const float4*)(ys + (n4 + 1) * YS_PITCH + i4);
        float4 yv2 = *(const float4*)(ys + (n4 + 2) * YS_PITCH + i4);
        float4 yv3 = *(const float4*)(ys + (n4 + 3) * YS_PITCH + i4);
        #pragma unroll
        for (int r = 0; r < 8; r++) {
            float4 wv = *(const float4*)(wws + (c0 + r) * 64 + i4);
            acc[r][0] = fmaf(wv.x, yv0.x, fmaf(wv.y, yv0.y, fmaf(wv.z, yv0.z, fmaf(wv.w, yv0.w, acc[r][0]))));
            acc[r][1] = fmaf(wv.x, yv1.x, fmaf(wv.y, yv1.y, fmaf(wv.z, yv1.z, fmaf(wv.w, yv1.w, acc[r][1]))));
            acc[r][2] = fmaf(wv.x, yv2.x, fmaf(wv.y, yv2.y, fmaf(wv.z, yv2.z, fmaf(wv.w, yv2.w, acc[r][2]))));
            acc[r][3] = fmaf(wv.x, yv3.x, fmaf(wv.y, yv3.y, fmaf(wv.z, yv3.z, fmaf(wv.w, yv3.w, acc[r][3]))));
        }
    }

    #pragma unroll
    for (int r = 0; r < 8; r++) {
        const int c = c0 + r;
        float wb = W_b[c];
        const size_t off = ((size_t)b * CC + c) * NN + n0 + n4;
        float4 xv = *(const float4*)(x + off);
        float4 ov = make_float4(acc[r][0] + wb + xv.x, acc[r][1] + wb + xv.y,
                                acc[r][2] + wb + xv.z, acc[r][3] + wb + xv.w);
        *(float4*)(out + off) = ov;
    }
}

// ---------------------------------------------------------------------------
// Launch
// ---------------------------------------------------------------------------
extern "C" void kernel_launch(void* const* d_in, const int* in_sizes, int n_in,
                              void* d_out, int out_size)
{
    const float* x       = (const float*)d_in[0];
    const float* g_w     = (const float*)d_in[1];
    const float* g_b     = (const float*)d_in[2];
    const float* theta_w = (const float*)d_in[3];
    const float* theta_b = (const float*)d_in[4];
    const float* phi_w   = (const float*)d_in[5];
    const float* phi_b   = (const float*)d_in[6];
    const float* W_w     = (const float*)d_in[7];
    const float* W_b     = (const float*)d_in[8];
    float* out = (float*)d_out;

    const int smem1 = (128 * 64 + 64 * 128) * 4;                           // 65536
    const int smem2 = (64 * QT_PITCH + 4 * 64 * 64 + 64 * PS_PITCH) * 4;   // 100352
    const int smem3 = (128 * 64 + 64 * YS_PITCH) * 4;                      // 50176

    cudaFuncSetAttribute(proj_kernel,    cudaFuncAttributeMaxDynamicSharedMemorySize, smem1);
    cudaFuncSetAttribute(flash_kernel,   cudaFuncAttributeMaxDynamicSharedMemorySize, smem2);
    cudaFuncSetAttribute(outproj_kernel, cudaFuncAttributeMaxDynamicSharedMemorySize, smem3);

    proj_kernel<<<dim3(NN / 64, 3, BB), 256, smem1>>>(
        x, g_w, g_b, theta_w, theta_b, phi_w, phi_b);
    flash_kernel<<<dim3(NN / 64, BB), 256, smem2>>>();
    outproj_kernel<<<dim3(NN / 64, BB), 256, smem3>>>(x, W_w, W_b, out);
}

// round 9
// speedup vs baseline: 2.3607x; 2.3607x over previous
#include <cuda_runtime.h>
#include <cuda_bf16.h>
#include <math.h>
#include <stdint.h>

// Problem constants
#define BB   4
#define CC   128
#define IC   64
#define NN   4096
#define NT   32          // 32 key tiles of 128

// ---------------------------------------------------------------------------
// Scratch (device globals)
// ---------------------------------------------------------------------------
__device__ __nv_bfloat16 d_th_hi[BB * NN * IC];   // theta [b][n][i]
__device__ __nv_bfloat16 d_th_lo[BB * NN * IC];
__device__ __nv_bfloat16 d_ph_hi[BB * NN * IC];   // phi^T [b][n][i]
__device__ __nv_bfloat16 d_ph_lo[BB * NN * IC];
__device__ __nv_bfloat16 d_g_hi [BB * NN * IC];   // g     [b][n][i]  (V layout)
__device__ __nv_bfloat16 d_g_lo [BB * NN * IC];
__device__ float         d_y    [BB * NN * IC];   // [b][n][i]

#define SW128(o) ((o) ^ (((o) >> 3) & 0x70))

__device__ __forceinline__ uint32_t smem_u32(const void* p) {
    uint32_t a;
    asm("{ .reg .u64 t; cvta.to.shared.u64 t, %1; cvt.u32.u64 %0, t; }" : "=r"(a) : "l"(p));
    return a;
}
__device__ __forceinline__ void ldsm_x4(uint32_t* r, uint32_t addr) {
    asm volatile("ldmatrix.sync.aligned.m8n8.x4.shared.b16 {%0,%1,%2,%3}, [%4];"
        : "=r"(r[0]), "=r"(r[1]), "=r"(r[2]), "=r"(r[3]) : "r"(addr));
}
__device__ __forceinline__ void ldsm_x4_t(uint32_t* r, uint32_t addr) {
    asm volatile("ldmatrix.sync.aligned.m8n8.x4.trans.shared.b16 {%0,%1,%2,%3}, [%4];"
        : "=r"(r[0]), "=r"(r[1]), "=r"(r[2]), "=r"(r[3]) : "r"(addr));
}
__device__ __forceinline__ void mma_bf16(float* d, const uint32_t* a, const uint32_t* b) {
    asm volatile("mma.sync.aligned.m16n8k16.row.col.f32.bf16.bf16.f32 "
        "{%0,%1,%2,%3}, {%4,%5,%6,%7}, {%8,%9}, {%0,%1,%2,%3};"
        : "+f"(d[0]), "+f"(d[1]), "+f"(d[2]), "+f"(d[3])
        : "r"(a[0]), "r"(a[1]), "r"(a[2]), "r"(a[3]), "r"(b[0]), "r"(b[1]));
}
__device__ __forceinline__ uint32_t pack2_bf16(float e0, float e1) {
    uint32_t r;   // lo half = e0, hi half = e1
    asm("cvt.rn.satfinite.bf16x2.f32 %0, %1, %2;" : "=r"(r) : "f"(e1), "f"(e0));
    return r;
}

// ---------------------------------------------------------------------------
// Kernel 1: projections -> bf16 hi/lo, all in [b][n][i] layout
// ---------------------------------------------------------------------------
__global__ __launch_bounds__(256)
void proj_kernel(const float* __restrict__ x,
                 const float* __restrict__ g_w,  const float* __restrict__ g_b,
                 const float* __restrict__ th_w, const float* __restrict__ th_b,
                 const float* __restrict__ ph_w, const float* __restrict__ ph_b)
{
    extern __shared__ float sm[];
    float* xs = sm;               // [128][64]
    float* ws = sm + 128 * 64;    // [64][128]

    const int n0 = blockIdx.x * 64;
    const int p  = blockIdx.y;
    const int b  = blockIdx.z;
    const float* w    = (p == 0) ? g_w : (p == 1) ? th_w : ph_w;
    const float* bias = (p == 0) ? g_b : (p == 1) ? th_b : ph_b;
    const int tid = threadIdx.x;

    {
        const float* xb = x + (size_t)b * CC * NN;
        const int n4 = (tid & 15) * 4;
        for (int c = (tid >> 4); c < 128; c += 16)
            *(float4*)(xs + c * 64 + n4) = *(const float4*)(xb + (size_t)c * NN + n0 + n4);
    }
    {
        const float4* src = (const float4*)w;
        float4* dst = (float4*)ws;
        for (int i = tid; i < 2048; i += 256) dst[i] = src[i];
    }
    __syncthreads();

    const int ty = tid >> 4, tx = tid & 15;
    const int i0 = ty * 4, j0 = tx * 4;

    float acc[4][4] = {};
    #pragma unroll 8
    for (int c = 0; c < 128; c++) {
        float4 xv = *(const float4*)(xs + c * 64 + j0);
        float w0 = ws[(i0 + 0) * 128 + c];
        float w1 = ws[(i0 + 1) * 128 + c];
        float w2 = ws[(i0 + 2) * 128 + c];
        float w3 = ws[(i0 + 3) * 128 + c];
        acc[0][0]=fmaf(w0,xv.x,acc[0][0]); acc[0][1]=fmaf(w0,xv.y,acc[0][1]);
        acc[0][2]=fmaf(w0,xv.z,acc[0][2]); acc[0][3]=fmaf(w0,xv.w,acc[0][3]);
        acc[1][0]=fmaf(w1,xv.x,acc[1][0]); acc[1][1]=fmaf(w1,xv.y,acc[1][1]);
        acc[1][2]=fmaf(w1,xv.z,acc[1][2]); acc[1][3]=fmaf(w1,xv.w,acc[1][3]);
        acc[2][0]=fmaf(w2,xv.x,acc[2][0]); acc[2][1]=fmaf(w2,xv.y,acc[2][1]);
        acc[2][2]=fmaf(w2,xv.z,acc[2][2]); acc[2][3]=fmaf(w2,xv.w,acc[2][3]);
        acc[3][0]=fmaf(w3,xv.x,acc[3][0]); acc[3][1]=fmaf(w3,xv.y,acc[3][1]);
        acc[3][2]=fmaf(w3,xv.z,acc[3][2]); acc[3][3]=fmaf(w3,xv.w,acc[3][3]);
    }

    __nv_bfloat16* dh = (p == 0) ? d_g_hi : (p == 1) ? d_th_hi : d_ph_hi;
    __nv_bfloat16* dl = (p == 0) ? d_g_lo : (p == 1) ? d_th_lo : d_ph_lo;
    float b0 = bias[i0], b1 = bias[i0+1], b2 = bias[i0+2], b3 = bias[i0+3];
    #pragma unroll
    for (int jj = 0; jj < 4; jj++) {
        float v0 = acc[0][jj] + b0, v1 = acc[1][jj] + b1;
        float v2 = acc[2][jj] + b2, v3 = acc[3][jj] + b3;
        __nv_bfloat16 h0 = __float2bfloat16(v0), h1 = __float2bfloat16(v1);
        __nv_bfloat16 h2 = __float2bfloat16(v2), h3 = __float2bfloat16(v3);
        uint2 hp, lp;
        hp.x = ((uint32_t)__bfloat16_as_ushort(h1) << 16) | __bfloat16_as_ushort(h0);
        hp.y = ((uint32_t)__bfloat16_as_ushort(h3) << 16) | __bfloat16_as_ushort(h2);
        lp.x = pack2_bf16(v0 - __bfloat162float(h0), v1 - __bfloat162float(h1));
        lp.y = pack2_bf16(v2 - __bfloat162float(h2), v3 - __bfloat162float(h3));
        size_t off = (size_t)(b * NN + n0 + j0 + jj) * IC + i0;
        *(uint2*)(dh + off) = hp;
        *(uint2*)(dl + off) = lp;
    }
}

// ---------------------------------------------------------------------------
// Kernel 2: flash attention via mma.sync bf16 hi/lo (base-ISA tensor cores)
// grid (32, B), 256 threads (8 warps, warp w owns q-rows r0 + 16w .. +15).
// smem: 6 tiles [128][64] bf16 SW128-swizzled = 96 KB.
// ---------------------------------------------------------------------------
static constexpr int T_TH_HI = 0;
static constexpr int T_TH_LO = 16384;
static constexpr int T_PH_HI = 32768;
static constexpr int T_PH_LO = 49152;
static constexpr int T_V_HI  = 65536;
static constexpr int T_V_LO  = 81920;
static constexpr int SM_FLASH = 98304;

// 128x64 bf16 tile, row-major src stride 64, SW128 dest
__device__ __forceinline__ void load_tile(char* dst, const __nv_bfloat16* src, int tid) {
    const int row = tid >> 1, half = tid & 1;
    const uint4* s = (const uint4*)(src + (size_t)row * 64 + half * 32);
    #pragma unroll
    for (int q = 0; q < 4; q++) {
        uint4 v = s[q];
        *(uint4*)(dst + SW128(row * 128 + half * 64 + q * 16)) = v;
    }
}

__global__ __launch_bounds__(256)
void flash_mma()
{
    extern __shared__ char smc[];
    const uint32_t smb = smem_u32(smc);
    const int tid = threadIdx.x, wid = tid >> 5, lane = tid & 31;
    const int b  = blockIdx.y;
    const int r0 = blockIdx.x * 128;

    const int lrow = lane & 7, lsel = lane >> 3;

    // prologue: theta tile (persistent whole kernel)
    load_tile(smc + T_TH_HI, d_th_hi + (size_t)(b * NN + r0) * IC, tid);
    load_tile(smc + T_TH_LO, d_th_lo + (size_t)(b * NN + r0) * IC, tid);

    float O[8][4];
    #pragma unroll
    for (int i = 0; i < 8; i++)
        #pragma unroll
        for (int j = 0; j < 4; j++) O[i][j] = 0.0f;
    float ls0 = 0.0f, ls1 = 0.0f;

    for (int t = 0; t < NT; t++) {
        if (t > 0) __syncthreads();   // prev tile's readers done
        load_tile(smc + T_PH_HI, d_ph_hi + (size_t)(b * NN + t * 128) * IC, tid);
        load_tile(smc + T_PH_LO, d_ph_lo + (size_t)(b * NN + t * 128) * IC, tid);
        load_tile(smc + T_V_HI,  d_g_hi  + (size_t)(b * NN + t * 128) * IC, tid);
        load_tile(smc + T_V_LO,  d_g_lo  + (size_t)(b * NN + t * 128) * IC, tid);
        __syncthreads();

        #pragma unroll
        for (int h = 0; h < 2; h++) {
            // ---- S = theta x phiT^T  (m16 x n64 per warp) ----
            float S[8][4];
            #pragma unroll
            for (int i = 0; i < 8; i++)
                #pragma unroll
                for (int j = 0; j < 4; j++) S[i][j] = 0.0f;

            #pragma unroll
            for (int kf = 0; kf < 4; kf++) {
                uint32_t Ah[4], Al[4];
                const int arow = wid * 16 + lrow + ((lsel & 1) << 3);
                const int acb  = kf * 32 + ((lsel >> 1) << 4);
                ldsm_x4(Ah, smb + T_TH_HI + SW128(arow * 128 + acb));
                ldsm_x4(Al, smb + T_TH_LO + SW128(arow * 128 + acb));
                #pragma unroll
                for (int nq = 0; nq < 4; nq++) {
                    uint32_t Bh[4], Bl[4];
                    const int brow = h * 64 + nq * 16 + lrow + ((lsel >> 1) << 3);
                    const int bcb  = kf * 32 + ((lsel & 1) << 4);
                    ldsm_x4(Bh, smb + T_PH_HI + SW128(brow * 128 + bcb));
                    ldsm_x4(Bl, smb + T_PH_LO + SW128(brow * 128 + bcb));
                    mma_bf16(S[2*nq],   Ah, Bh);
                    mma_bf16(S[2*nq],   Ah, Bl);
                    mma_bf16(S[2*nq],   Al, Bh);
                    mma_bf16(S[2*nq+1], Ah, Bh + 2);
                    mma_bf16(S[2*nq+1], Ah, Bl + 2);
                    mma_bf16(S[2*nq+1], Al, Bh + 2);
                }
            }

            // ---- softmax (no max subtraction; logits bounded) + repack to A-frags
            uint32_t Ph[4][4], Pl[4][4];
            #pragma unroll
            for (int nb = 0; nb < 8; nb++) {
                float e0 = __expf(S[nb][0]);
                float e1 = __expf(S[nb][1]);
                float e2 = __expf(S[nb][2]);
                float e3 = __expf(S[nb][3]);
                ls0 += e0 + e1;
                ls1 += e2 + e3;
                __nv_bfloat16 h0 = __float2bfloat16(e0), h1 = __float2bfloat16(e1);
                __nv_bfloat16 h2 = __float2bfloat16(e2), h3 = __float2bfloat16(e3);
                const int kf2 = nb >> 1, sub = (nb & 1) * 2;
                Ph[kf2][sub + 0] = ((uint32_t)__bfloat16_as_ushort(h1) << 16) | __bfloat16_as_ushort(h0);
                Ph[kf2][sub + 1] = ((uint32_t)__bfloat16_as_ushort(h3) << 16) | __bfloat16_as_ushort(h2);
                Pl[kf2][sub + 0] = pack2_bf16(e0 - __bfloat162float(h0), e1 - __bfloat162float(h1));
                Pl[kf2][sub + 1] = pack2_bf16(e2 - __bfloat162float(h2), e3 - __bfloat162float(h3));
            }

            // ---- O += P x V  (keys h*64..h*64+63, j 0..63) ----
            #pragma unroll
            for (int kf2 = 0; kf2 < 4; kf2++) {
                #pragma unroll
                for (int jq = 0; jq < 4; jq++) {
                    uint32_t Vh[4], Vl[4];
                    const int vrow = h * 64 + kf2 * 16 + lrow + ((lsel & 1) << 3);
                    const int vcb  = jq * 32 + ((lsel >> 1) << 4);
                    ldsm_x4_t(Vh, smb + T_V_HI + SW128(vrow * 128 + vcb));
                    ldsm_x4_t(Vl, smb + T_V_LO + SW128(vrow * 128 + vcb));
                    mma_bf16(O[2*jq],   Ph[kf2], Vh);
                    mma_bf16(O[2*jq],   Ph[kf2], Vl);
                    mma_bf16(O[2*jq],   Pl[kf2], Vh);
                    mma_bf16(O[2*jq+1], Ph[kf2], Vh + 2);
                    mma_bf16(O[2*jq+1], Ph[kf2], Vl + 2);
                    mma_bf16(O[2*jq+1], Pl[kf2], Vh + 2);
                }
            }
        }
    }

    // row-sum reduction over the 4 lanes sharing lane/4
    ls0 += __shfl_xor_sync(0xffffffffu, ls0, 1);
    ls0 += __shfl_xor_sync(0xffffffffu, ls0, 2);
    ls1 += __shfl_xor_sync(0xffffffffu, ls1, 1);
    ls1 += __shfl_xor_sync(0xffffffffu, ls1, 2);
    const float inv0 = 1.0f / ls0, inv1 = 1.0f / ls1;

    const int gr0 = r0 + wid * 16 + (lane >> 2);
    float* yb = d_y + (size_t)b * NN * IC;
    #pragma unroll
    for (int jb = 0; jb < 8; jb++) {
        const int col = jb * 8 + (lane & 3) * 2;
        *(float2*)(yb + (size_t)gr0 * IC + col) =
            make_float2(O[jb][0] * inv0, O[jb][1] * inv0);
        *(float2*)(yb + (size_t)(gr0 + 8) * IC + col) =
            make_float2(O[jb][2] * inv1, O[jb][3] * inv1);
    }
}

// ---------------------------------------------------------------------------
// Kernel 3: output projection + residual
// ---------------------------------------------------------------------------
#define YS_PITCH 68

__global__ __launch_bounds__(256)
void outproj_kernel(const float* __restrict__ x,
                    const float* __restrict__ W_w,
                    const float* __restrict__ W_b,
                    float* __restrict__ out)
{
    extern __shared__ float sm[];
    float* wws = sm;
    float* ys  = sm + 128 * 64;

    const int n0  = blockIdx.x * 64;
    const int b   = blockIdx.y;
    const int tid = threadIdx.x;

    {
        const float4* src = (const float4*)W_w;
        float4* dst = (float4*)wws;
        for (int i = tid; i < 2048; i += 256) dst[i] = src[i];
    }
    {
        const float* yb = d_y + (size_t)b * NN * IC;
        const int i4 = (tid & 15) * 4;
        for (int n = (tid >> 4); n < 64; n += 16)
            *(float4*)(ys + n * YS_PITCH + i4) = *(const float4*)(yb + (size_t)(n0 + n) * IC + i4);
    }
    __syncthreads();

    const int ty = tid >> 4, tx = tid & 15;
    const int c0 = ty * 8, n4 = tx * 4;

    float acc[8][4] = {};
    #pragma unroll 4
    for (int i4 = 0; i4 < 64; i4 += 4) {
        float4 yv0 = *(const float4*)(ys + (n4 + 0) * YS_PITCH + i4);
        float4 yv1 = *(const float4*)(ys + (n4 + 1) * YS_PITCH + i4);
        float4 yv2 = *(const float4*)(ys + (n4 + 2) * YS_PITCH + i4);
        float4 yv3 = *(const float4*)(ys + (n4 + 3) * YS_PITCH + i4);
        #pragma unroll
        for (int r = 0; r < 8; r++) {
            float4 wv = *(const float4*)(wws + (c0 + r) * 64 + i4);
            acc[r][0] = fmaf(wv.x, yv0.x, fmaf(wv.y, yv0.y, fmaf(wv.z, yv0.z, fmaf(wv.w, yv0.w, acc[r][0]))));
            acc[r][1] = fmaf(wv.x, yv1.x, fmaf(wv.y, yv1.y, fmaf(wv.z, yv1.z, fmaf(wv.w, yv1.w, acc[r][1]))));
            acc[r][2] = fmaf(wv.x, yv2.x, fmaf(wv.y, yv2.y, fmaf(wv.z, yv2.z, fmaf(wv.w, yv2.w, acc[r][2]))));
            acc[r][3] = fmaf(wv.x, yv3.x, fmaf(wv.y, yv3.y, fmaf(wv.z, yv3.z, fmaf(wv.w, yv3.w, acc[r][3]))));
        }
    }

    #pragma unroll
    for (int r = 0; r < 8; r++) {
        const int c = c0 + r;
        float wb = W_b[c];
        const size_t off = ((size_t)b * CC + c) * NN + n0 + n4;
        float4 xv = *(const float4*)(x + off);
        float4 ov = make_float4(acc[r][0] + wb + xv.x, acc[r][1] + wb + xv.y,
                                acc[r][2] + wb + xv.z, acc[r][3] + wb + xv.w);
        *(float4*)(out + off) = ov;
    }
}

// ---------------------------------------------------------------------------
// Launch
// ---------------------------------------------------------------------------
extern "C" void kernel_launch(void* const* d_in, const int* in_sizes, int n_in,
                              void* d_out, int out_size)
{
    const float* x       = (const float*)d_in[0];
    const float* g_w     = (const float*)d_in[1];
    const float* g_b     = (const float*)d_in[2];
    const float* theta_w = (const float*)d_in[3];
    const float* theta_b = (const float*)d_in[4];
    const float* phi_w   = (const float*)d_in[5];
    const float* phi_b   = (const float*)d_in[6];
    const float* W_w     = (const float*)d_in[7];
    const float* W_b     = (const float*)d_in[8];
    float* out = (float*)d_out;

    const int smem1 = (128 * 64 + 64 * 128) * 4;          // 65536
    const int smem2 = SM_FLASH;                           // 98304
    const int smem3 = (128 * 64 + 64 * YS_PITCH) * 4;     // 50176

    cudaFuncSetAttribute(proj_kernel,    cudaFuncAttributeMaxDynamicSharedMemorySize, smem1);
    cudaFuncSetAttribute(flash_mma,      cudaFuncAttributeMaxDynamicSharedMemorySize, smem2);
    cudaFuncSetAttribute(outproj_kernel, cudaFuncAttributeMaxDynamicSharedMemorySize, smem3);

    proj_kernel<<<dim3(NN / 64, 3, BB), 256, smem1>>>(
        x, g_w, g_b, theta_w, theta_b, phi_w, phi_b);
    flash_mma<<<dim3(NN / 128, BB), 256, smem2>>>();
    outproj_kernel<<<dim3(NN / 64, BB), 256, smem3>>>(x, W_w, W_b, out);
}

// round 12
// speedup vs baseline: 3.0532x; 1.2933x over previous
#include <cuda_runtime.h>
#include <cuda_bf16.h>
#include <cuda_fp16.h>
#include <math.h>
#include <stdint.h>

// Problem constants
#define BB   4
#define CC   128
#define IC   64
#define NN   4096
#define NT   32          // 32 key tiles of 128

// ---------------------------------------------------------------------------
// Scratch (device globals) — fp16 operands
// ---------------------------------------------------------------------------
__device__ __half d_th_hi[BB * NN * IC];   // theta hi [b][n][i]
__device__ __half d_th_lo[BB * NN * IC];   // theta lo
__device__ __half d_ph   [BB * NN * IC];   // phi^T (hi only) [b][n][i]
__device__ __half d_g    [BB * NN * IC];   // g (hi only)     [b][n][i]
__device__ float  d_y    [BB * NN * IC];   // [b][n][i]

#define SW128(o) ((o) ^ (((o) >> 3) & 0x70))

__device__ __forceinline__ uint32_t smem_u32(const void* p) {
    uint32_t a;
    asm("{ .reg .u64 t; cvta.to.shared.u64 t, %1; cvt.u32.u64 %0, t; }" : "=r"(a) : "l"(p));
    return a;
}
__device__ __forceinline__ void ldsm_x4(uint32_t* r, uint32_t addr) {
    asm volatile("ldmatrix.sync.aligned.m8n8.x4.shared.b16 {%0,%1,%2,%3}, [%4];"
        : "=r"(r[0]), "=r"(r[1]), "=r"(r[2]), "=r"(r[3]) : "r"(addr));
}
__device__ __forceinline__ void ldsm_x4_t(uint32_t* r, uint32_t addr) {
    asm volatile("ldmatrix.sync.aligned.m8n8.x4.trans.shared.b16 {%0,%1,%2,%3}, [%4];"
        : "=r"(r[0]), "=r"(r[1]), "=r"(r[2]), "=r"(r[3]) : "r"(addr));
}
__device__ __forceinline__ void mma_f16(float* d, const uint32_t* a, const uint32_t* b) {
    asm volatile("mma.sync.aligned.m16n8k16.row.col.f32.f16.f16.f32 "
        "{%0,%1,%2,%3}, {%4,%5,%6,%7}, {%8,%9}, {%0,%1,%2,%3};"
        : "+f"(d[0]), "+f"(d[1]), "+f"(d[2]), "+f"(d[3])
        : "r"(a[0]), "r"(a[1]), "r"(a[2]), "r"(a[3]), "r"(b[0]), "r"(b[1]));
}
// pack two fp16: first operand -> LOW half (order proven by R9's passing bf16 twin)
__device__ __forceinline__ uint32_t pack2_f16(float lo_val, float hi_val) {
    uint32_t r;
    asm("cvt.rn.f16x2.f32 %0, %1, %2;" : "=r"(r) : "f"(hi_val), "f"(lo_val));
    return r;
}
__device__ __forceinline__ uint32_t packbits_f16(__half lo, __half hi) {
    return ((uint32_t)__half_as_ushort(hi) << 16) | __half_as_ushort(lo);
}

// ---------------------------------------------------------------------------
// Kernel 1: projections -> fp16 operands, [b][n][i] layout.
//   theta: hi + lo.   phi, g: hi only.
// ---------------------------------------------------------------------------
__global__ __launch_bounds__(256)
void proj_kernel(const float* __restrict__ x,
                 const float* __restrict__ g_w,  const float* __restrict__ g_b,
                 const float* __restrict__ th_w, const float* __restrict__ th_b,
                 const float* __restrict__ ph_w, const float* __restrict__ ph_b)
{
    extern __shared__ float sm[];
    float* xs = sm;               // [128][64]
    float* ws = sm + 128 * 64;    // [64][128]

    const int n0 = blockIdx.x * 64;
    const int p  = blockIdx.y;
    const int b  = blockIdx.z;
    const float* w    = (p == 0) ? g_w : (p == 1) ? th_w : ph_w;
    const float* bias = (p == 0) ? g_b : (p == 1) ? th_b : ph_b;
    const int tid = threadIdx.x;

    {
        const float* xb = x + (size_t)b * CC * NN;
        const int n4 = (tid & 15) * 4;
        for (int c = (tid >> 4); c < 128; c += 16)
            *(float4*)(xs + c * 64 + n4) = *(const float4*)(xb + (size_t)c * NN + n0 + n4);
    }
    {
        const float4* src = (const float4*)w;
        float4* dst = (float4*)ws;
        for (int i = tid; i < 2048; i += 256) dst[i] = src[i];
    }
    __syncthreads();

    const int ty = tid >> 4, tx = tid & 15;
    const int i0 = ty * 4, j0 = tx * 4;

    float acc[4][4] = {};
    #pragma unroll 8
    for (int c = 0; c < 128; c++) {
        float4 xv = *(const float4*)(xs + c * 64 + j0);
        float w0 = ws[(i0 + 0) * 128 + c];
        float w1 = ws[(i0 + 1) * 128 + c];
        float w2 = ws[(i0 + 2) * 128 + c];
        float w3 = ws[(i0 + 3) * 128 + c];
        acc[0][0]=fmaf(w0,xv.x,acc[0][0]); acc[0][1]=fmaf(w0,xv.y,acc[0][1]);
        acc[0][2]=fmaf(w0,xv.z,acc[0][2]); acc[0][3]=fmaf(w0,xv.w,acc[0][3]);
        acc[1][0]=fmaf(w1,xv.x,acc[1][0]); acc[1][1]=fmaf(w1,xv.y,acc[1][1]);
        acc[1][2]=fmaf(w1,xv.z,acc[1][2]); acc[1][3]=fmaf(w1,xv.w,acc[1][3]);
        acc[2][0]=fmaf(w2,xv.x,acc[2][0]); acc[2][1]=fmaf(w2,xv.y,acc[2][1]);
        acc[2][2]=fmaf(w2,xv.z,acc[2][2]); acc[2][3]=fmaf(w2,xv.w,acc[2][3]);
        acc[3][0]=fmaf(w3,xv.x,acc[3][0]); acc[3][1]=fmaf(w3,xv.y,acc[3][1]);
        acc[3][2]=fmaf(w3,xv.z,acc[3][2]); acc[3][3]=fmaf(w3,xv.w,acc[3][3]);
    }

    float b0 = bias[i0], b1 = bias[i0+1], b2 = bias[i0+2], b3 = bias[i0+3];
    if (p == 1) {
        // theta: hi + lo
        #pragma unroll
        for (int jj = 0; jj < 4; jj++) {
            float v0 = acc[0][jj] + b0, v1 = acc[1][jj] + b1;
            float v2 = acc[2][jj] + b2, v3 = acc[3][jj] + b3;
            __half h0 = __float2half_rn(v0), h1 = __float2half_rn(v1);
            __half h2 = __float2half_rn(v2), h3 = __float2half_rn(v3);
            uint2 hp, lp;
            hp.x = packbits_f16(h0, h1);
            hp.y = packbits_f16(h2, h3);
            lp.x = pack2_f16(v0 - __half2float(h0), v1 - __half2float(h1));
            lp.y = pack2_f16(v2 - __half2float(h2), v3 - __half2float(h3));
            size_t off = (size_t)(b * NN + n0 + j0 + jj) * IC + i0;
            *(uint2*)(d_th_hi + off) = hp;
            *(uint2*)(d_th_lo + off) = lp;
        }
    } else {
        __half* dst = (p == 0) ? d_g : d_ph;
        #pragma unroll
        for (int jj = 0; jj < 4; jj++) {
            float v0 = acc[0][jj] + b0, v1 = acc[1][jj] + b1;
            float v2 = acc[2][jj] + b2, v3 = acc[3][jj] + b3;
            uint2 hp;
            hp.x = pack2_f16(v0, v1);
            hp.y = pack2_f16(v2, v3);
            size_t off = (size_t)(b * NN + n0 + j0 + jj) * IC + i0;
            *(uint2*)(dst + off) = hp;
        }
    }
}

// ---------------------------------------------------------------------------
// Kernel 2: flash attention, fp16 mma.sync, 2-term precision:
//   S = (theta_hi + theta_lo) x phi_hi^T     (2 MMAs per position)
//   P = exp(S - rowmax)  (online max; P<=1 fits fp16), split P -> Ph+Pl in regs
//   O += (Ph + Pl) x V_hi                    (2 MMAs per position)
// grid (32, B), 256 threads. smem: theta hi/lo (32KB) + double-buffered
// phi/V tiles (4 x 16KB) = 96KB.
// ---------------------------------------------------------------------------
static constexpr int T_TH_HI = 0;
static constexpr int T_TH_LO = 16384;
static constexpr int T_PH0   = 32768;
static constexpr int T_V0    = 49152;
static constexpr int T_PH1   = 65536;
static constexpr int T_V1    = 81920;
static constexpr int SM_FLASH = 98304;

// 128x64 fp16 tile, row-major src stride 64, SW128 dest
__device__ __forceinline__ void load_tile(char* dst, const __half* src, int tid) {
    const int row = tid >> 1, half = tid & 1;
    const uint4* s = (const uint4*)(src + (size_t)row * 64 + half * 32);
    #pragma unroll
    for (int q = 0; q < 4; q++) {
        uint4 v = s[q];
        *(uint4*)(dst + SW128(row * 128 + half * 64 + q * 16)) = v;
    }
}

__global__ __launch_bounds__(256)
void flash_mma()
{
    extern __shared__ char smc[];
    const uint32_t smb = smem_u32(smc);
    const int tid = threadIdx.x, wid = tid >> 5, lane = tid & 31;
    const int b  = blockIdx.y;
    const int r0 = blockIdx.x * 128;

    const int lrow = lane & 7, lsel = lane >> 3;

    // theta tiles (persistent)
    load_tile(smc + T_TH_HI, d_th_hi + (size_t)(b * NN + r0) * IC, tid);
    load_tile(smc + T_TH_LO, d_th_lo + (size_t)(b * NN + r0) * IC, tid);
    // tile 0 -> buffer 0
    load_tile(smc + T_PH0, d_ph + (size_t)(b * NN) * IC, tid);
    load_tile(smc + T_V0,  d_g  + (size_t)(b * NN) * IC, tid);

    // stage tile 1 in regs
    const int srow = tid >> 1, shalf = tid & 1;
    uint4 pst[4], vst[4];
    {
        const uint4* ps = (const uint4*)(d_ph + (size_t)(b * NN + 128 + srow) * IC + shalf * 32);
        const uint4* vs = (const uint4*)(d_g  + (size_t)(b * NN + 128 + srow) * IC + shalf * 32);
        #pragma unroll
        for (int q = 0; q < 4; q++) { pst[q] = ps[q]; vst[q] = vs[q]; }
    }

    float O[8][4];
    #pragma unroll
    for (int i = 0; i < 8; i++)
        #pragma unroll
        for (int j = 0; j < 4; j++) O[i][j] = 0.0f;
    float ls0 = 0.0f, ls1 = 0.0f;
    float m0 = -1e30f, m1 = -1e30f;

    for (int t = 0; t < NT; t++) {
        __syncthreads();   // prev readers of buf[(t+1)&1] done; buf[t&1] stores visible

        // commit staged tile t+1 into the other buffer
        if (t + 1 < NT) {
            char* pd = smc + ((t & 1) ? T_PH0 : T_PH1);
            char* vd = smc + ((t & 1) ? T_V0 : T_V1);
            #pragma unroll
            for (int q = 0; q < 4; q++) {
                *(uint4*)(pd + SW128(srow * 128 + shalf * 64 + q * 16)) = pst[q];
                *(uint4*)(vd + SW128(srow * 128 + shalf * 64 + q * 16)) = vst[q];
            }
        }
        // prefetch tile t+2 into regs
        if (t + 2 < NT) {
            const uint4* ps = (const uint4*)(d_ph + (size_t)(b * NN + (t + 2) * 128 + srow) * IC + shalf * 32);
            const uint4* vs = (const uint4*)(d_g  + (size_t)(b * NN + (t + 2) * 128 + srow) * IC + shalf * 32);
            #pragma unroll
            for (int q = 0; q < 4; q++) { pst[q] = ps[q]; vst[q] = vs[q]; }
        }

        const int TPH = (t & 1) ? T_PH1 : T_PH0;
        const int TV  = (t & 1) ? T_V1  : T_V0;

        #pragma unroll
        for (int h = 0; h < 2; h++) {
            // ---- S = theta x phi^T ----
            float S[8][4];
            #pragma unroll
            for (int i = 0; i < 8; i++)
                #pragma unroll
                for (int j = 0; j < 4; j++) S[i][j] = 0.0f;

            #pragma unroll
            for (int kf = 0; kf < 4; kf++) {
                uint32_t Ah[4], Al[4];
                const int arow = wid * 16 + lrow + ((lsel & 1) << 3);
                const int acb  = kf * 32 + ((lsel >> 1) << 4);
                ldsm_x4(Ah, smb + T_TH_HI + SW128(arow * 128 + acb));
                ldsm_x4(Al, smb + T_TH_LO + SW128(arow * 128 + acb));
                #pragma unroll
                for (int nq = 0; nq < 4; nq++) {
                    uint32_t Bh[4];
                    const int brow = h * 64 + nq * 16 + lrow + ((lsel >> 1) << 3);
                    const int bcb  = kf * 32 + ((lsel & 1) << 4);
                    ldsm_x4(Bh, smb + TPH + SW128(brow * 128 + bcb));
                    mma_f16(S[2*nq],   Ah, Bh);
                    mma_f16(S[2*nq],   Al, Bh);
                    mma_f16(S[2*nq+1], Ah, Bh + 2);
                    mma_f16(S[2*nq+1], Al, Bh + 2);
                }
            }

            // ---- online-max softmax, P -> fp16 hi/lo in regs ----
            float hm0 = -1e30f, hm1 = -1e30f;
            #pragma unroll
            for (int nb = 0; nb < 8; nb++) {
                hm0 = fmaxf(hm0, fmaxf(S[nb][0], S[nb][1]));
                hm1 = fmaxf(hm1, fmaxf(S[nb][2], S[nb][3]));
            }
            hm0 = fmaxf(hm0, __shfl_xor_sync(0xffffffffu, hm0, 1));
            hm0 = fmaxf(hm0, __shfl_xor_sync(0xffffffffu, hm0, 2));
            hm1 = fmaxf(hm1, __shfl_xor_sync(0xffffffffu, hm1, 1));
            hm1 = fmaxf(hm1, __shfl_xor_sync(0xffffffffu, hm1, 2));
            const float m0n = fmaxf(m0, hm0), m1n = fmaxf(m1, hm1);
            const float sc0 = __expf(m0 - m0n), sc1 = __expf(m1 - m1n);
            m0 = m0n; m1 = m1n;
            ls0 *= sc0; ls1 *= sc1;
            #pragma unroll
            for (int i = 0; i < 8; i++) {
                O[i][0] *= sc0; O[i][1] *= sc0;
                O[i][2] *= sc1; O[i][3] *= sc1;
            }

            uint32_t Ph[4][4], Pl[4][4];
            #pragma unroll
            for (int nb = 0; nb < 8; nb++) {
                float e0 = __expf(S[nb][0] - m0n);
                float e1 = __expf(S[nb][1] - m0n);
                float e2 = __expf(S[nb][2] - m1n);
                float e3 = __expf(S[nb][3] - m1n);
                ls0 += e0 + e1;
                ls1 += e2 + e3;
                __half h0 = __float2half_rn(e0), h1 = __float2half_rn(e1);
                __half h2 = __float2half_rn(e2), h3 = __float2half_rn(e3);
                const int kf2 = nb >> 1, sub = (nb & 1) * 2;
                Ph[kf2][sub + 0] = packbits_f16(h0, h1);
                Ph[kf2][sub + 1] = packbits_f16(h2, h3);
                Pl[kf2][sub + 0] = pack2_f16(e0 - __half2float(h0), e1 - __half2float(h1));
                Pl[kf2][sub + 1] = pack2_f16(e2 - __half2float(h2), e3 - __half2float(h3));
            }

            // ---- O += P x V ----
            #pragma unroll
            for (int kf2 = 0; kf2 < 4; kf2++) {
                #pragma unroll
                for (int jq = 0; jq < 4; jq++) {
                    uint32_t Vh[4];
                    const int vrow = h * 64 + kf2 * 16 + lrow + ((lsel & 1) << 3);
                    const int vcb  = jq * 32 + ((lsel >> 1) << 4);
                    ldsm_x4_t(Vh, smb + TV + SW128(vrow * 128 + vcb));
                    mma_f16(O[2*jq],   Ph[kf2], Vh);
                    mma_f16(O[2*jq],   Pl[kf2], Vh);
                    mma_f16(O[2*jq+1], Ph[kf2], Vh + 2);
                    mma_f16(O[2*jq+1], Pl[kf2], Vh + 2);
                }
            }
        }
    }

    // row-sum reduce across the 4 lanes of each row
    ls0 += __shfl_xor_sync(0xffffffffu, ls0, 1);
    ls0 += __shfl_xor_sync(0xffffffffu, ls0, 2);
    ls1 += __shfl_xor_sync(0xffffffffu, ls1, 1);
    ls1 += __shfl_xor_sync(0xffffffffu, ls1, 2);
    const float inv0 = 1.0f / ls0, inv1 = 1.0f / ls1;

    const int gr0 = r0 + wid * 16 + (lane >> 2);
    float* yb = d_y + (size_t)b * NN * IC;
    #pragma unroll
    for (int jb = 0; jb < 8; jb++) {
        const int col = jb * 8 + (lane & 3) * 2;
        *(float2*)(yb + (size_t)gr0 * IC + col) =
            make_float2(O[jb][0] * inv0, O[jb][1] * inv0);
        *(float2*)(yb + (size_t)(gr0 + 8) * IC + col) =
            make_float2(O[jb][2] * inv1, O[jb][3] * inv1);
    }
}

// ---------------------------------------------------------------------------
// Kernel 3: output projection + residual
// ---------------------------------------------------------------------------
#define YS_PITCH 68

__global__ __launch_bounds__(256)
void outproj_kernel(const float* __restrict__ x,
                    const float* __restrict__ W_w,
                    const float* __restrict__ W_b,
                    float* __restrict__ out)
{
    extern __shared__ float sm[];
    float* wws = sm;
    float* ys  = sm + 128 * 64;

    const int n0  = blockIdx.x * 64;
    const int b   = blockIdx.y;
    const int tid = threadIdx.x;

    {
        const float4* src = (const float4*)W_w;
        float4* dst = (float4*)wws;
        for (int i = tid; i < 2048; i += 256) dst[i] = src[i];
    }
    {
        const float* yb = d_y + (size_t)b * NN * IC;
        const int i4 = (tid & 15) * 4;
        for (int n = (tid >> 4); n < 64; n += 16)
            *(float4*)(ys + n * YS_PITCH + i4) = *(const float4*)(yb + (size_t)(n0 + n) * IC + i4);
    }
    __syncthreads();

    const int ty = tid >> 4, tx = tid & 15;
    const int c0 = ty * 8, n4 = tx * 4;

    float acc[8][4] = {};
    #pragma unroll 4
    for (int i4 = 0; i4 < 64; i4 += 4) {
        float4 yv0 = *(const float4*)(ys + (n4 + 0) * YS_PITCH + i4);
        float4 yv1 = *(const float4*)(ys + (n4 + 1) * YS_PITCH + i4);
        float4 yv2 = *(const float4*)(ys + (n4 + 2) * YS_PITCH + i4);
        float4 yv3 = *(const float4*)(ys + (n4 + 3) * YS_PITCH + i4);
        #pragma unroll
        for (int r = 0; r < 8; r++) {
            float4 wv = *(const float4*)(wws + (c0 + r) * 64 + i4);
            acc[r][0] = fmaf(wv.x, yv0.x, fmaf(wv.y, yv0.y, fmaf(wv.z, yv0.z, fmaf(wv.w, yv0.w, acc[r][0]))));
            acc[r][1] = fmaf(wv.x, yv1.x, fmaf(wv.y, yv1.y, fmaf(wv.z, yv1.z, fmaf(wv.w, yv1.w, acc[r][1]))));
            acc[r][2] = fmaf(wv.x, yv2.x, fmaf(wv.y, yv2.y, fmaf(wv.z, yv2.z, fmaf(wv.w, yv2.w, acc[r][2]))));
            acc[r][3] = fmaf(wv.x, yv3.x, fmaf(wv.y, yv3.y, fmaf(wv.z, yv3.z, fmaf(wv.w, yv3.w, acc[r][3]))));
        }
    }

    #pragma unroll
    for (int r = 0; r < 8; r++) {
        const int c = c0 + r;
        float wb = W_b[c];
        const size_t off = ((size_t)b * CC + c) * NN + n0 + n4;
        float4 xv = *(const float4*)(x + off);
        float4 ov = make_float4(acc[r][0] + wb + xv.x, acc[r][1] + wb + xv.y,
                                acc[r][2] + wb + xv.z, acc[r][3] + wb + xv.w);
        *(float4*)(out + off) = ov;
    }
}

// ---------------------------------------------------------------------------
// Launch
// ---------------------------------------------------------------------------
extern "C" void kernel_launch(void* const* d_in, const int* in_sizes, int n_in,
                              void* d_out, int out_size)
{
    const float* x       = (const float*)d_in[0];
    const float* g_w     = (const float*)d_in[1];
    const float* g_b     = (const float*)d_in[2];
    const float* theta_w = (const float*)d_in[3];
    const float* theta_b = (const float*)d_in[4];
    const float* phi_w   = (const float*)d_in[5];
    const float* phi_b   = (const float*)d_in[6];
    const float* W_w     = (const float*)d_in[7];
    const float* W_b     = (const float*)d_in[8];
    float* out = (float*)d_out;

    const int smem1 = (128 * 64 + 64 * 128) * 4;          // 65536
    const int smem2 = SM_FLASH;                           // 98304
    const int smem3 = (128 * 64 + 64 * YS_PITCH) * 4;     // 50176

    cudaFuncSetAttribute(proj_kernel,    cudaFuncAttributeMaxDynamicSharedMemorySize, smem1);
    cudaFuncSetAttribute(flash_mma,      cudaFuncAttributeMaxDynamicSharedMemorySize, smem2);
    cudaFuncSetAttribute(outproj_kernel, cudaFuncAttributeMaxDynamicSharedMemorySize, smem3);

    proj_kernel<<<dim3(NN / 64, 3, BB), 256, smem1>>>(
        x, g_w, g_b, theta_w, theta_b, phi_w, phi_b);
    flash_mma<<<dim3(NN / 128, BB), 256, smem2>>>();
    outproj_kernel<<<dim3(NN / 64, BB), 256, smem3>>>(x, W_w, W_b, out);
}